// round 7
// baseline (speedup 1.0000x reference)
#include <cuda_runtime.h>
#include <cuda_bf16.h>

// DCN-v1 cross network, algebraically collapsed, single kernel.
//   x_{l+1} = input*(x_l.w_l) + x_l + b_l  =>  x_l = A_l*input + B_l,
//   B_l = sum_{k<l} b_k,   A_{l+1} = A_l*(1+u_l) + t_l,
//   u_l = input.w_l (ORIGINAL input),  t_l = sum_{k<l} b_k.w_l.
// Per row: one fused 6-dot pass, scalar recurrence, out = A*input + sum_b.
// Cross terms + sum_b are computed per-CTA in the shadow of the input DRAM
// loads (no prologue kernel). B=16384, D=1024, L=6. One warp per row.
// HBM floor = 128 MB (input+output) ~= 16us @ 8TB/s.

#define CN_B 16384
#define CN_D 1024
#define CN_L 6
#define CN_R 8              // rows per CTA = warps per CTA
#define CN_THREADS 256
#define CN_D4 (CN_D / 4)    // 256 float4 per row (== CN_THREADS)
#define CN_J 8              // float4s per lane (32 lanes * 8 = 256)
#define CN_NP 15            // pairs (k<l), k,l in [0,6)

// pid -> (k,l) tables packed 4 bits/entry (pid = l*(l-1)/2 + k):
//   PK = {0,0,1,0,1,2,0,1,2,3,0,1,2,3,4}
//   PL = {1,2,2,3,3,3,4,4,4,4,5,5,5,5,5}
#define CN_PK_BITS 0x4321043210210100ull
#define CN_PL_BITS 0x5555544443332210ull

__global__ __launch_bounds__(CN_THREADS)
void cross_network_kernel(const float* __restrict__ input,
                          const float* __restrict__ W,
                          const float* __restrict__ bias,
                          float* __restrict__ out)
{
    const int tid  = threadIdx.x;
    const int lane = tid & 31;
    const int warp = tid >> 5;

    __shared__ float sP[CN_NP];                   // P[pid] = b_k . w_l
    __shared__ __align__(16) float4 sumb4[CN_D4]; // sum_k b_k (full row)

    const size_t row = (size_t)blockIdx.x * CN_R + warp;
    const float4* in4 = reinterpret_cast<const float4*>(input) + row * CN_D4;
    const float4* W4  = reinterpret_cast<const float4*>(W);
    const float4* b4  = reinterpret_cast<const float4*>(bias);

    // ---- 1) Issue this warp's input loads first (DRAM, in flight). ----
    float4 xin[CN_J];
#pragma unroll
    for (int j = 0; j < CN_J; ++j)
        xin[j] = __ldcs(in4 + lane + 32 * j);     // streaming: keep L1 for W/b

    // ---- 2) Hidden under the loads: cross terms P and sum_b. ----
#pragma unroll
    for (int t = 0; t < 2; ++t) {
        const int pid = warp + t * CN_R;
        if (pid < CN_NP) {
            const int pk = (int)((CN_PK_BITS >> (4 * pid)) & 0xF);
            const int pl = (int)((CN_PL_BITS >> (4 * pid)) & 0xF);
            const float4* wl = W4 + pl * CN_D4;
            const float4* bk = b4 + pk * CN_D4;
            float s = 0.f;
#pragma unroll
            for (int j = 0; j < CN_J; ++j) {
                const float4 wv = __ldg(wl + lane + 32 * j);
                const float4 bv = __ldg(bk + lane + 32 * j);
                s = fmaf(bv.x, wv.x, s);
                s = fmaf(bv.y, wv.y, s);
                s = fmaf(bv.z, wv.z, s);
                s = fmaf(bv.w, wv.w, s);
            }
#pragma unroll
            for (int o = 16; o > 0; o >>= 1)
                s += __shfl_xor_sync(0xffffffffu, s, o);
            if (lane == 0) sP[pid] = s;
        }
    }

    // sum_b staged once per CTA (all warps share these slices later).
    {
        float4 c = make_float4(0.f, 0.f, 0.f, 0.f);
#pragma unroll
        for (int k = 0; k < CN_L; ++k) {
            const float4 bv = __ldg(b4 + k * CN_D4 + tid);
            c.x += bv.x; c.y += bv.y; c.z += bv.z; c.w += bv.w;
        }
        sumb4[tid] = c;
    }

    __syncthreads();   // the only barrier

    // ---- 3) Fused pass: u_l = input . w_l for all 6 layers. ----
    float s[CN_L];
#pragma unroll
    for (int l = 0; l < CN_L; ++l) s[l] = 0.f;
#pragma unroll
    for (int l = 0; l < CN_L; ++l) {
        const float4* wl = W4 + l * CN_D4;
#pragma unroll
        for (int j = 0; j < CN_J; ++j) {
            const float4 wv = __ldg(wl + lane + 32 * j);
            s[l] = fmaf(xin[j].x, wv.x, s[l]);
            s[l] = fmaf(xin[j].y, wv.y, s[l]);
            s[l] = fmaf(xin[j].z, wv.z, s[l]);
            s[l] = fmaf(xin[j].w, wv.w, s[l]);
        }
    }

    // 6 butterfly reduces, overlapped (all lanes end with full dots).
#pragma unroll
    for (int o = 16; o > 0; o >>= 1) {
#pragma unroll
        for (int l = 0; l < CN_L; ++l)
            s[l] += __shfl_xor_sync(0xffffffffu, s[l], o);
    }

    // ---- 4) Scalar recurrence: A_{l+1} = A_l*(1+u_l) + t_l. ----
    float A = 1.f;
#pragma unroll
    for (int l = 0; l < CN_L; ++l) {
        float t = 0.f;
#pragma unroll
        for (int k = 0; k < l; ++k)
            t += sP[l * (l - 1) / 2 + k];
        A = fmaf(A, s[l], A) + t;
    }

    // ---- 5) out = A*input + sum_b. ----
    float4* out4 = reinterpret_cast<float4*>(out) + row * CN_D4;
#pragma unroll
    for (int j = 0; j < CN_J; ++j) {
        const float4 c = sumb4[lane + 32 * j];
        float4 o;
        o.x = fmaf(xin[j].x, A, c.x);
        o.y = fmaf(xin[j].y, A, c.y);
        o.z = fmaf(xin[j].z, A, c.z);
        o.w = fmaf(xin[j].w, A, c.w);
        __stcs(out4 + lane + 32 * j, o);
    }
}

extern "C" void kernel_launch(void* const* d_in, const int* in_sizes, int n_in,
                              void* d_out, int out_size)
{
    const float* input = (const float*)d_in[0];
    const float* W     = (const float*)d_in[1];
    const float* b     = (const float*)d_in[2];
    float* out         = (float*)d_out;

    cross_network_kernel<<<CN_B / CN_R, CN_THREADS>>>(input, W, b, out);
}